// round 9
// baseline (speedup 1.0000x reference)
#include <cuda_runtime.h>
#include <cstdint>
#include <math.h>

#define NH 16
#define NB 2
#define NS 2048
#define DM 1024
#define DK 64
#define NROWS (NS*NB)   // 4096

// Scratch (allocation-free rule: __device__ globals)
__device__ __align__(16) float g_Q[NH*NB*NS*DK];
__device__ __align__(16) float g_K[NH*NB*NS*DK];
__device__ __align__(16) float g_V[NH*NB*NS*DK];
__device__ __align__(16) float g_ctx[(size_t)NROWS*DM];

// ---------------------------------------------------------------------------
// helpers (portable mma.sync path — compute_103 has no tcgen05)
// ---------------------------------------------------------------------------
__device__ __forceinline__ uint32_t f2tf32(float f) {
    uint32_t o;
    asm("cvt.rna.tf32.f32 %0, %1;" : "=r"(o) : "f"(f));
    return o;
}
__device__ __forceinline__ float ex2(float x) {
    float r;
    asm("ex2.approx.ftz.f32 %0, %1;" : "=f"(r) : "f"(x));
    return r;
}
__device__ __forceinline__ void mma_tf32(float c[4], const uint32_t a[4], const uint32_t b[2]) {
    asm volatile(
        "mma.sync.aligned.m16n8k8.row.col.f32.tf32.tf32.f32 "
        "{%0,%1,%2,%3}, {%4,%5,%6,%7}, {%8,%9}, {%0,%1,%2,%3};"
        : "+f"(c[0]), "+f"(c[1]), "+f"(c[2]), "+f"(c[3])
        : "r"(a[0]), "r"(a[1]), "r"(a[2]), "r"(a[3]), "r"(b[0]), "r"(b[1]));
}
__device__ __forceinline__ uint4 cvt4(float4 v) {
    uint4 u;
    u.x = f2tf32(v.x); u.y = f2tf32(v.y); u.z = f2tf32(v.z); u.w = f2tf32(v.w);
    return u;
}
__device__ __forceinline__ uint32_t smem_u32(const void* p) {
    uint32_t a;
    asm("{ .reg .u64 t; cvta.to.shared.u64 t, %1; cvt.u32.u64 %0, t; }" : "=r"(a) : "l"(p));
    return a;
}
__device__ __forceinline__ void cp_async16(uint32_t dst, const void* src) {
    asm volatile("cp.async.cg.shared.global [%0], [%1], 16;" :: "r"(dst), "l"(src));
}
__device__ __forceinline__ void cp_commit() { asm volatile("cp.async.commit_group;" ::: "memory"); }
template<int N> __device__ __forceinline__ void cp_wait() {
    asm volatile("cp.async.wait_group %0;" :: "n"(N) : "memory");
}

// ---------------------------------------------------------------------------
// tf32 mma.sync NT GEMM: out = X[.,DM] @ W[DM,DM]^T + bias
// 128x128 tile, BK=16, 256 thr / 8 warps (2x4), warp 64x32.
// k-permuted XOR-swizzled smem: element (r,k) at r*16 + 4*((k%4)^swz(r)) + k/4,
// swz(r) = (r&3)^((r>>2)&3). Fragments (k = {t,t+4,t+8,t+12}) load as ONE
// LDS.128 covering both k8 steps; cvt.rna on the store path (once/element).
// Conflict-free loads AND stores (checked against 32-bank crossbar).
// Register-prefetch LDG pipeline, double-buffered (R5-proven).
// MODE 0: scatter into [h, b, s, dk]; MODE 1: row-major [NROWS, DM]
// ---------------------------------------------------------------------------
#define BM 128
#define BN 128
#define BK 16

template<int MODE>
__device__ __forceinline__ void gemm_body(const float* __restrict__ X,
                                          const float* __restrict__ W,
                                          const float* __restrict__ bias,
                                          float* __restrict__ out,
                                          int rT, int cT)
{
    __shared__ __align__(16) uint32_t As[2][BM * 16];
    __shared__ __align__(16) uint32_t Bs[2][BN * 16];

    const int tid = threadIdx.x;
    const int wid = tid >> 5, lid = tid & 31;
    const int wm  = wid >> 2;
    const int wn  = wid & 3;
    const int g   = lid >> 2;
    const int t   = lid & 3;

    // loader coords: thread covers rows lr0 and lr0+64, k-chunk lc4
    const int lr0 = tid >> 2;          // 0..63
    const int lc4 = tid & 3;           // float4 k-chunk (k = 4*lc4 + d)
    const int sw  = (lr0 & 3) ^ ((lr0 >> 2) & 3);
    int so[4];
    #pragma unroll
    for (int d = 0; d < 4; d++) so[d] = lr0 * 16 + 4 * (d ^ sw) + lc4;

    const float* xr0 = &X[(size_t)(rT + lr0) * DM + 4 * lc4];
    const float* xr1 = xr0 + (size_t)64 * DM;
    const float* wr0 = &W[(size_t)(cT + lr0) * DM + 4 * lc4];
    const float* wr1 = wr0 + (size_t)64 * DM;

    // fragment read swizzle (lane-constant): rows/cols ≡ g (mod 16 group)
    const int fsw = 4 * (t ^ (g & 3) ^ (g >> 2));

    // prefetch chunk 0
    float4 ra0 = *(const float4*)xr0;
    float4 ra1 = *(const float4*)xr1;
    float4 rb0 = *(const float4*)wr0;
    float4 rb1 = *(const float4*)wr1;

    float acc[4][4][4] = {};
    const int NCHUNK = DM / BK;   // 64
    for (int c = 0; c < NCHUNK; c++) {
        const int p = c & 1;
        __syncthreads();           // everyone done reading buffer p
        {
            uint4 u;
            u = cvt4(ra0);
            As[p][so[0]] = u.x; As[p][so[1]] = u.y;
            As[p][so[2]] = u.z; As[p][so[3]] = u.w;
            u = cvt4(ra1);
            As[p][so[0] + 1024] = u.x; As[p][so[1] + 1024] = u.y;
            As[p][so[2] + 1024] = u.z; As[p][so[3] + 1024] = u.w;
            u = cvt4(rb0);
            Bs[p][so[0]] = u.x; Bs[p][so[1]] = u.y;
            Bs[p][so[2]] = u.z; Bs[p][so[3]] = u.w;
            u = cvt4(rb1);
            Bs[p][so[0] + 1024] = u.x; Bs[p][so[1] + 1024] = u.y;
            Bs[p][so[2] + 1024] = u.z; Bs[p][so[3] + 1024] = u.w;
        }
        __syncthreads();

        if (c + 1 < NCHUNK) {      // prefetch next chunk (latency under compute)
            const int kk = (c + 1) << 4;
            ra0 = *(const float4*)(xr0 + kk);
            ra1 = *(const float4*)(xr1 + kk);
            rb0 = *(const float4*)(wr0 + kk);
            rb1 = *(const float4*)(wr1 + kk);
        }

        uint32_t aks0[4][4], aks8[4][4];
        #pragma unroll
        for (int mt = 0; mt < 4; mt++) {
            const int rbase = (wm * 64 + mt * 16 + g) * 16;
            const uint4 va = *(const uint4*)&As[p][rbase + fsw];
            const uint4 vb = *(const uint4*)&As[p][rbase + 128 + (fsw ^ 8)];
            aks0[mt][0] = va.x; aks0[mt][1] = vb.x; aks0[mt][2] = va.y; aks0[mt][3] = vb.y;
            aks8[mt][0] = va.z; aks8[mt][1] = vb.z; aks8[mt][2] = va.w; aks8[mt][3] = vb.w;
        }
        uint32_t bk0[4][2], bk8[4][2];
        #pragma unroll
        for (int nt = 0; nt < 4; nt++) {
            const int cbase = (wn * 32 + nt * 8 + g) * 16;
            const uint4 v = *(const uint4*)&Bs[p][cbase + (fsw ^ (8 * (nt & 1)))];
            bk0[nt][0] = v.x; bk0[nt][1] = v.y;
            bk8[nt][0] = v.z; bk8[nt][1] = v.w;
        }
        #pragma unroll
        for (int mt = 0; mt < 4; mt++)
            #pragma unroll
            for (int nt = 0; nt < 4; nt++)
                mma_tf32(acc[mt][nt], aks0[mt], bk0[nt]);
        #pragma unroll
        for (int mt = 0; mt < 4; mt++)
            #pragma unroll
            for (int nt = 0; nt < 4; nt++)
                mma_tf32(acc[mt][nt], aks8[mt], bk8[nt]);
    }

    #pragma unroll
    for (int mt = 0; mt < 4; mt++) {
        #pragma unroll
        for (int nt = 0; nt < 4; nt++) {
            const int col = cT + wn * 32 + nt * 8 + 2 * t;
            const float bx = bias[col], by = bias[col + 1];
            #pragma unroll
            for (int half = 0; half < 2; half++) {
                const int row = rT + wm * 64 + mt * 16 + g + half * 8;
                float2 o;
                o.x = acc[mt][nt][half * 2 + 0] + bx;
                o.y = acc[mt][nt][half * 2 + 1] + by;
                if (MODE == 0) {
                    const int h = col >> 6, dk = col & 63;
                    const int s = row >> 1, b = row & 1;
                    *(float2*)&out[(((size_t)(h * NB + b) * NS + s) << 6) + dk] = o;
                } else {
                    *(float2*)&out[(size_t)row * DM + col] = o;
                }
            }
        }
    }
}

__global__ __launch_bounds__(256, 2)
void qkv_gemm_kernel(const float* __restrict__ q, const float* __restrict__ k,
                     const float* __restrict__ v,
                     const float* __restrict__ Wq, const float* __restrict__ Wk,
                     const float* __restrict__ Wv,
                     const float* __restrict__ bq, const float* __restrict__ bk,
                     const float* __restrict__ bv,
                     float* oq, float* ok, float* ov)
{
    const float *X, *W, *B;
    float* O;
    if (blockIdx.z == 0)      { X = q; W = Wq; B = bq; O = oq; }
    else if (blockIdx.z == 1) { X = k; W = Wk; B = bk; O = ok; }
    else                      { X = v; W = Wv; B = bv; O = ov; }
    gemm_body<0>(X, W, B, O, blockIdx.y << 7, blockIdx.x << 7);
}

__global__ __launch_bounds__(256, 2)
void out_gemm_kernel(const float* __restrict__ X, const float* __restrict__ W,
                     const float* __restrict__ B, float* O)
{
    gemm_body<1>(X, W, B, O, blockIdx.y << 7, blockIdx.x << 7);
}

// ---------------------------------------------------------------------------
// Flash attention (unchanged from R8): tf32 mma.sync + cp.async double-
// buffered raw-fp32 K/V consumed as truncated tf32.
// ---------------------------------------------------------------------------
#define TQ 128
#define KS_STRIDE 68
#define VS_STRIDE 72
#define PS_STRIDE 68
#define ATT_STG (64 * KS_STRIDE + 64 * VS_STRIDE)   // 8960 u32 per stage
#define PS_OFF (2 * ATT_STG)                        // 17920
#define ATT_SMEM_U32 (PS_OFF + TQ * PS_STRIDE)      // 26624
#define ATT_SMEM_BYTES (ATT_SMEM_U32 * 4)           // 106496

#define QSCALE (0.125f * 1.4426950408889634f)

__global__ __launch_bounds__(256, 2)
void attn_mma_kernel(const float* __restrict__ Qg_,
                     const float* __restrict__ Kg_,
                     const float* __restrict__ Vg_,
                     float* __restrict__ ctx)
{
    extern __shared__ uint32_t sm[];
    const uint32_t smb = smem_u32(sm);

    const int tid = threadIdx.x;
    const int wid = tid >> 5, lid = tid & 31;
    const int g   = lid >> 2, t = lid & 3;
    const int wrow = wid * 16;
    const int qt = blockIdx.x;
    const int hb = blockIdx.y;

    const float* Qg = Qg_ + ((size_t)hb * NS << 6);
    const float* Kg = Kg_ + ((size_t)hb * NS << 6);
    const float* Vg = Vg_ + ((size_t)hb * NS << 6);

    const int akey = tid >> 4;
    const int ad0  = (tid & 15) * 4;

    {
        #pragma unroll
        for (int it = 0; it < 4; it++) {
            const int key = akey + it * 16;
            const size_t src = ((size_t)key << 6) + ad0;
            cp_async16(smb + (uint32_t)(key * KS_STRIDE + ad0) * 4, &Kg[src]);
            cp_async16(smb + (uint32_t)(64 * KS_STRIDE + key * VS_STRIDE + ad0) * 4, &Vg[src]);
        }
        cp_commit();
    }

    float* Qf = (float*)(sm + PS_OFF);
    #pragma unroll
    for (int it = 0; it < 8; it++) {
        const int flat = it * 256 + tid;
        const int row = flat >> 4, d0 = (flat & 15) * 4;
        float4 q4 = *(const float4*)&Qg[((size_t)(qt * TQ + row) << 6) + d0];
        q4.x *= QSCALE; q4.y *= QSCALE; q4.z *= QSCALE; q4.w *= QSCALE;
        *(float4*)&Qf[row * PS_STRIDE + d0] = q4;
    }
    __syncthreads();

    uint32_t qa[8][4];
    #pragma unroll
    for (int ks = 0; ks < 8; ks++) {
        qa[ks][0] = f2tf32(Qf[(wrow + g)     * PS_STRIDE + ks * 8 + t]);
        qa[ks][1] = f2tf32(Qf[(wrow + g + 8) * PS_STRIDE + ks * 8 + t]);
        qa[ks][2] = f2tf32(Qf[(wrow + g)     * PS_STRIDE + ks * 8 + t + 4]);
        qa[ks][3] = f2tf32(Qf[(wrow + g + 8) * PS_STRIDE + ks * 8 + t + 4]);
    }

    float oacc[8][4] = {};
    float m0 = -1e30f, m1 = -1e30f, l0 = 0.f, l1 = 0.f;

    const int NT = NS / 64;
    for (int kt = 0; kt < NT; kt++) {
        cp_wait<0>();
        __syncthreads();

        if (kt + 1 < NT) {
            const uint32_t sb = ((kt + 1) & 1) * (ATT_STG * 4);
            #pragma unroll
            for (int it = 0; it < 4; it++) {
                const int key = akey + it * 16;
                const size_t src = ((size_t)((kt + 1) * 64 + key) << 6) + ad0;
                cp_async16(smb + sb + (uint32_t)(key * KS_STRIDE + ad0) * 4, &Kg[src]);
                cp_async16(smb + sb + (uint32_t)(64 * KS_STRIDE + key * VS_STRIDE + ad0) * 4, &Vg[src]);
            }
        }
        cp_commit();

        const uint32_t* Kb = sm + (kt & 1) * ATT_STG;
        const uint32_t* Vb = Kb + 64 * KS_STRIDE;

        float sacc[8][4] = {};
        #pragma unroll
        for (int nt = 0; nt < 8; nt++) {
            const uint32_t* krow = &Kb[(nt * 8 + g) * KS_STRIDE + t];
            #pragma unroll
            for (int ks = 0; ks < 8; ks++) {
                uint32_t b[2];
                b[0] = krow[ks * 8];
                b[1] = krow[ks * 8 + 4];
                mma_tf32(sacc[nt], qa[ks], b);
            }
        }

        float mx0 = -1e30f, mx1 = -1e30f;
        #pragma unroll
        for (int nt = 0; nt < 8; nt++) {
            mx0 = fmaxf(mx0, fmaxf(sacc[nt][0], sacc[nt][1]));
            mx1 = fmaxf(mx1, fmaxf(sacc[nt][2], sacc[nt][3]));
        }
        mx0 = fmaxf(mx0, __shfl_xor_sync(0xffffffffu, mx0, 1));
        mx0 = fmaxf(mx0, __shfl_xor_sync(0xffffffffu, mx0, 2));
        mx1 = fmaxf(mx1, __shfl_xor_sync(0xffffffffu, mx1, 1));
        mx1 = fmaxf(mx1, __shfl_xor_sync(0xffffffffu, mx1, 2));
        const float mn0 = fmaxf(m0, mx0), mn1 = fmaxf(m1, mx1);
        const float c0 = ex2(m0 - mn0), c1 = ex2(m1 - mn1);
        m0 = mn0; m1 = mn1;

        float s0 = 0.f, s1 = 0.f;
        #pragma unroll
        for (int nt = 0; nt < 8; nt++) {
            const float e0 = ex2(sacc[nt][0] - mn0);
            const float e1 = ex2(sacc[nt][1] - mn0);
            const float e2 = ex2(sacc[nt][2] - mn1);
            const float e3 = ex2(sacc[nt][3] - mn1);
            s0 += e0 + e1; s1 += e2 + e3;
            uint2 p;
            p.x = f2tf32(e0); p.y = f2tf32(e1);
            *(uint2*)&sm[PS_OFF + (wrow + g) * PS_STRIDE + nt * 8 + 2 * t] = p;
            p.x = f2tf32(e2); p.y = f2tf32(e3);
            *(uint2*)&sm[PS_OFF + (wrow + g + 8) * PS_STRIDE + nt * 8 + 2 * t] = p;
            oacc[nt][0] *= c0; oacc[nt][1] *= c0;
            oacc[nt][2] *= c1; oacc[nt][3] *= c1;
        }
        s0 += __shfl_xor_sync(0xffffffffu, s0, 1);
        s0 += __shfl_xor_sync(0xffffffffu, s0, 2);
        s1 += __shfl_xor_sync(0xffffffffu, s1, 1);
        s1 += __shfl_xor_sync(0xffffffffu, s1, 2);
        l0 = l0 * c0 + s0;
        l1 = l1 * c1 + s1;
        __syncwarp();

        #pragma unroll
        for (int ks = 0; ks < 8; ks++) {
            uint32_t pa[4];
            pa[0] = sm[PS_OFF + (wrow + g)     * PS_STRIDE + ks * 8 + t];
            pa[1] = sm[PS_OFF + (wrow + g + 8) * PS_STRIDE + ks * 8 + t];
            pa[2] = sm[PS_OFF + (wrow + g)     * PS_STRIDE + ks * 8 + t + 4];
            pa[3] = sm[PS_OFF + (wrow + g + 8) * PS_STRIDE + ks * 8 + t + 4];
            const uint32_t* vrow0 = &Vb[(ks * 8 + t)     * VS_STRIDE + g];
            const uint32_t* vrow1 = &Vb[(ks * 8 + t + 4) * VS_STRIDE + g];
            #pragma unroll
            for (int nt = 0; nt < 8; nt++) {
                uint32_t b[2];
                b[0] = vrow0[nt * 8];
                b[1] = vrow1[nt * 8];
                mma_tf32(oacc[nt], pa, b);
            }
        }
    }

    const float inv0 = 1.f / l0, inv1 = 1.f / l1;
    const int h = hb >> 1, b = hb & 1;
    const int s_0 = qt * TQ + wrow + g;
    const int s_1 = s_0 + 8;
    #pragma unroll
    for (int nt = 0; nt < 8; nt++) {
        const int col = (h << 6) + nt * 8 + 2 * t;
        float2 o;
        o.x = oacc[nt][0] * inv0; o.y = oacc[nt][1] * inv0;
        *(float2*)&ctx[(size_t)(s_0 * NB + b) * DM + col] = o;
        o.x = oacc[nt][2] * inv1; o.y = oacc[nt][3] * inv1;
        *(float2*)&ctx[(size_t)(s_1 * NB + b) * DM + col] = o;
    }
}

// ---------------------------------------------------------------------------
extern "C" void kernel_launch(void* const* d_in, const int* in_sizes, int n_in,
                              void* d_out, int out_size)
{
    const float* query = (const float*)d_in[0];
    const float* key_  = (const float*)d_in[1];
    const float* value = (const float*)d_in[2];
    const float* Wq = (const float*)d_in[3];
    const float* bq = (const float*)d_in[4];
    const float* Wk = (const float*)d_in[5];
    const float* bk = (const float*)d_in[6];
    const float* Wv = (const float*)d_in[7];
    const float* bv = (const float*)d_in[8];
    const float* Wo = (const float*)d_in[9];
    const float* bo = (const float*)d_in[10];
    float* out = (float*)d_out;

    float *pQ, *pK, *pV, *pC;
    cudaGetSymbolAddress((void**)&pQ, g_Q);
    cudaGetSymbolAddress((void**)&pK, g_K);
    cudaGetSymbolAddress((void**)&pV, g_V);
    cudaGetSymbolAddress((void**)&pC, g_ctx);

    cudaFuncSetAttribute(attn_mma_kernel,
                         cudaFuncAttributeMaxDynamicSharedMemorySize, ATT_SMEM_BYTES);

    dim3 gq(DM / BN, NROWS / BM, 3);   // 8 x 32 x 3 = 768 CTAs
    qkv_gemm_kernel<<<gq, 256>>>(query, key_, value, Wq, Wk, Wv,
                                 bq, bk, bv, pQ, pK, pV);

    attn_mma_kernel<<<dim3(NS / TQ, NH * NB), 256, ATT_SMEM_BYTES>>>(pQ, pK, pV, pC);

    dim3 gg(DM / BN, NROWS / BM);      // 8 x 32 = 256 CTAs
    out_gemm_kernel<<<gg, 256>>>(pC, Wo, bo, out);
}

// round 10
// speedup vs baseline: 1.3379x; 1.3379x over previous
#include <cuda_runtime.h>
#include <cstdint>
#include <math.h>

#define NH 16
#define NB 2
#define NS 2048
#define DM 1024
#define DK 64
#define NROWS (NS*NB)   // 4096

// Scratch (allocation-free rule: __device__ globals)
__device__ __align__(16) float g_Q[NH*NB*NS*DK];
__device__ __align__(16) float g_K[NH*NB*NS*DK];
__device__ __align__(16) float g_V[NH*NB*NS*DK];
__device__ __align__(16) float g_ctx[(size_t)NROWS*DM];

// ---------------------------------------------------------------------------
// helpers (portable mma.sync path — compute_103 has no tcgen05)
// ---------------------------------------------------------------------------
__device__ __forceinline__ uint32_t f2tf32(float f) {
    uint32_t o;
    asm("cvt.rna.tf32.f32 %0, %1;" : "=r"(o) : "f"(f));
    return o;
}
__device__ __forceinline__ float ex2(float x) {
    float r;
    asm("ex2.approx.ftz.f32 %0, %1;" : "=f"(r) : "f"(x));
    return r;
}
__device__ __forceinline__ void mma_tf32(float c[4], const uint32_t a[4], const uint32_t b[2]) {
    asm volatile(
        "mma.sync.aligned.m16n8k8.row.col.f32.tf32.tf32.f32 "
        "{%0,%1,%2,%3}, {%4,%5,%6,%7}, {%8,%9}, {%0,%1,%2,%3};"
        : "+f"(c[0]), "+f"(c[1]), "+f"(c[2]), "+f"(c[3])
        : "r"(a[0]), "r"(a[1]), "r"(a[2]), "r"(a[3]), "r"(b[0]), "r"(b[1]));
}
__device__ __forceinline__ uint4 cvt4(float4 v) {
    uint4 u;
    u.x = f2tf32(v.x); u.y = f2tf32(v.y); u.z = f2tf32(v.z); u.w = f2tf32(v.w);
    return u;
}
__device__ __forceinline__ uint32_t smem_u32(const void* p) {
    uint32_t a;
    asm("{ .reg .u64 t; cvta.to.shared.u64 t, %1; cvt.u32.u64 %0, t; }" : "=r"(a) : "l"(p));
    return a;
}
__device__ __forceinline__ void cp_async16(uint32_t dst, const void* src) {
    asm volatile("cp.async.cg.shared.global [%0], [%1], 16;" :: "r"(dst), "l"(src));
}
__device__ __forceinline__ void cp_commit() { asm volatile("cp.async.commit_group;" ::: "memory"); }
template<int N> __device__ __forceinline__ void cp_wait() {
    asm volatile("cp.async.wait_group %0;" :: "n"(N) : "memory");
}

// ---------------------------------------------------------------------------
// tf32 mma.sync NT GEMM (R5 variant — best measured: qkv 217us).
// 128x128 tile, BK=16, 256 thr / 8 warps (2x4), warp 64x32.
// cvt.rna on store path, register-prefetch double buffer, stride-20 smem.
// MODE 0: scatter into [h, b, s, dk]; MODE 1: row-major [NROWS, DM]
// ---------------------------------------------------------------------------
#define BM 128
#define BN 128
#define BK 16
#define LDS_STRIDE 20

template<int MODE>
__device__ __forceinline__ void gemm_body(const float* __restrict__ X,
                                          const float* __restrict__ W,
                                          const float* __restrict__ bias,
                                          float* __restrict__ out,
                                          int rT, int cT)
{
    __shared__ __align__(16) uint32_t As[2][BM * LDS_STRIDE];
    __shared__ __align__(16) uint32_t Bs[2][BN * LDS_STRIDE];

    const int tid = threadIdx.x;
    const int wid = tid >> 5, lid = tid & 31;
    const int wm  = wid >> 2;
    const int wn  = wid & 3;
    const int g   = lid >> 2;
    const int t   = lid & 3;

    const int lr0 = (tid * 4) >> 4;
    const int lr1 = lr0 + 64;
    const int lc  = (tid * 4) & 15;

    float acc[4][4][4] = {};
    float4 ra0, ra1, rb0, rb1;

    ra0 = *(const float4*)&X[(size_t)(rT + lr0) * DM + lc];
    ra1 = *(const float4*)&X[(size_t)(rT + lr1) * DM + lc];
    rb0 = *(const float4*)&W[(size_t)(cT + lr0) * DM + lc];
    rb1 = *(const float4*)&W[(size_t)(cT + lr1) * DM + lc];
    *(uint4*)&As[0][lr0 * LDS_STRIDE + lc] = cvt4(ra0);
    *(uint4*)&As[0][lr1 * LDS_STRIDE + lc] = cvt4(ra1);
    *(uint4*)&Bs[0][lr0 * LDS_STRIDE + lc] = cvt4(rb0);
    *(uint4*)&Bs[0][lr1 * LDS_STRIDE + lc] = cvt4(rb1);

    const int NCHUNK = DM / BK;
    for (int c = 0; c < NCHUNK; c++) {
        const int p = c & 1;
        __syncthreads();

        if (c + 1 < NCHUNK) {
            const int kk = (c + 1) << 4;
            ra0 = *(const float4*)&X[(size_t)(rT + lr0) * DM + kk + lc];
            ra1 = *(const float4*)&X[(size_t)(rT + lr1) * DM + kk + lc];
            rb0 = *(const float4*)&W[(size_t)(cT + lr0) * DM + kk + lc];
            rb1 = *(const float4*)&W[(size_t)(cT + lr1) * DM + kk + lc];
        }

        #pragma unroll
        for (int ks = 0; ks < BK; ks += 8) {
            uint32_t a[4][4], b[4][2];
            #pragma unroll
            for (int mt = 0; mt < 4; mt++) {
                const int row = wm * 64 + mt * 16 + g;
                a[mt][0] = As[p][row * LDS_STRIDE + ks + t];
                a[mt][1] = As[p][(row + 8) * LDS_STRIDE + ks + t];
                a[mt][2] = As[p][row * LDS_STRIDE + ks + t + 4];
                a[mt][3] = As[p][(row + 8) * LDS_STRIDE + ks + t + 4];
            }
            #pragma unroll
            for (int nt = 0; nt < 4; nt++) {
                const int col = wn * 32 + nt * 8 + g;
                b[nt][0] = Bs[p][col * LDS_STRIDE + ks + t];
                b[nt][1] = Bs[p][col * LDS_STRIDE + ks + t + 4];
            }
            #pragma unroll
            for (int mt = 0; mt < 4; mt++)
                #pragma unroll
                for (int nt = 0; nt < 4; nt++)
                    mma_tf32(acc[mt][nt], a[mt], b[nt]);
        }

        if (c + 1 < NCHUNK) {
            const int q = (c + 1) & 1;
            *(uint4*)&As[q][lr0 * LDS_STRIDE + lc] = cvt4(ra0);
            *(uint4*)&As[q][lr1 * LDS_STRIDE + lc] = cvt4(ra1);
            *(uint4*)&Bs[q][lr0 * LDS_STRIDE + lc] = cvt4(rb0);
            *(uint4*)&Bs[q][lr1 * LDS_STRIDE + lc] = cvt4(rb1);
        }
    }

    #pragma unroll
    for (int mt = 0; mt < 4; mt++) {
        #pragma unroll
        for (int nt = 0; nt < 4; nt++) {
            const int col = cT + wn * 32 + nt * 8 + 2 * t;
            const float bx = bias[col], by = bias[col + 1];
            #pragma unroll
            for (int half = 0; half < 2; half++) {
                const int row = rT + wm * 64 + mt * 16 + g + half * 8;
                float2 o;
                o.x = acc[mt][nt][half * 2 + 0] + bx;
                o.y = acc[mt][nt][half * 2 + 1] + by;
                if (MODE == 0) {
                    const int h = col >> 6, dk = col & 63;
                    const int s = row >> 1, b = row & 1;
                    *(float2*)&out[(((size_t)(h * NB + b) * NS + s) << 6) + dk] = o;
                } else {
                    *(float2*)&out[(size_t)row * DM + col] = o;
                }
            }
        }
    }
}

__global__ __launch_bounds__(256, 2)
void qkv_gemm_kernel(const float* __restrict__ q, const float* __restrict__ k,
                     const float* __restrict__ v,
                     const float* __restrict__ Wq, const float* __restrict__ Wk,
                     const float* __restrict__ Wv,
                     const float* __restrict__ bq, const float* __restrict__ bk,
                     const float* __restrict__ bv,
                     float* oq, float* ok, float* ov)
{
    const float *X, *W, *B;
    float* O;
    if (blockIdx.z == 0)      { X = q; W = Wq; B = bq; O = oq; }
    else if (blockIdx.z == 1) { X = k; W = Wk; B = bk; O = ok; }
    else                      { X = v; W = Wv; B = bv; O = ov; }
    gemm_body<0>(X, W, B, O, blockIdx.y << 7, blockIdx.x << 7);
}

__global__ __launch_bounds__(256, 2)
void out_gemm_kernel(const float* __restrict__ X, const float* __restrict__ W,
                     const float* __restrict__ B, float* O)
{
    gemm_body<1>(X, W, B, O, blockIdx.y << 7, blockIdx.x << 7);
}

// ---------------------------------------------------------------------------
// Flash attention, tf32 mma.sync + cp.async double-buffered K/V + REGISTER P.
// CTA = 128 q-rows of one (h,b); 256 threads / 8 warps (16 rows each).
// P never touches smem: PV key order is permuted (A-pos a <-> C-pos
// a<4?2a:2a-7), so the S C-fragments' exp() values ARE the PV A-fragments,
// and the B-side reads V rows 8ks+2t / 8ks+2t+1 instead (stride 68 ->
// conflict-free: banks 8t+g and 8t+4+g, bijective over the warp).
// K/V raw fp32 in smem, consumed as truncated tf32. Q staged in stage-1
// buffer before the pipeline first writes it.
// ---------------------------------------------------------------------------
#define TQ 128
#define KS_STRIDE 68
#define VS_STRIDE 68
#define ATT_STG (64 * KS_STRIDE + 64 * VS_STRIDE)   // 8704 u32 per stage
#define ATT_SMEM_U32 (2 * ATT_STG)                  // 17408
#define ATT_SMEM_BYTES (ATT_SMEM_U32 * 4)           // 69632

#define QSCALE (0.125f * 1.4426950408889634f)

__global__ __launch_bounds__(256, 2)
void attn_mma_kernel(const float* __restrict__ Qg_,
                     const float* __restrict__ Kg_,
                     const float* __restrict__ Vg_,
                     float* __restrict__ ctx)
{
    extern __shared__ uint32_t sm[];
    const uint32_t smb = smem_u32(sm);

    const int tid = threadIdx.x;
    const int wid = tid >> 5, lid = tid & 31;
    const int g   = lid >> 2, t = lid & 3;
    const int wrow = wid * 16;
    const int qt = blockIdx.x;
    const int hb = blockIdx.y;

    const float* Qg = Qg_ + ((size_t)hb * NS << 6);
    const float* Kg = Kg_ + ((size_t)hb * NS << 6);
    const float* Vg = Vg_ + ((size_t)hb * NS << 6);

    const int akey = tid >> 4;            // 0..15 base key (4 rounds of +16)
    const int ad0  = (tid & 15) * 4;      // d offset

    // Prologue: stage 0 <- tile 0
    {
        #pragma unroll
        for (int it = 0; it < 4; it++) {
            const int key = akey + it * 16;
            const size_t src = ((size_t)key << 6) + ad0;
            cp_async16(smb + (uint32_t)(key * KS_STRIDE + ad0) * 4, &Kg[src]);
            cp_async16(smb + (uint32_t)(64 * KS_STRIDE + key * VS_STRIDE + ad0) * 4, &Vg[src]);
        }
        cp_commit();
    }

    // Stage Q (pre-scaled into log2 domain) into STAGE-1 area (not yet used
    // by the pipeline), build A frags, then the first loop syncthreads
    // separates these reads from the tile-1 cp.async writes.
    float* Qf = (float*)(sm + ATT_STG);
    #pragma unroll
    for (int it = 0; it < 8; it++) {
        const int flat = it * 256 + tid;      // < 2048
        const int row = flat >> 4, d0 = (flat & 15) * 4;
        float4 q4 = *(const float4*)&Qg[((size_t)(qt * TQ + row) << 6) + d0];
        q4.x *= QSCALE; q4.y *= QSCALE; q4.z *= QSCALE; q4.w *= QSCALE;
        *(float4*)&Qf[row * KS_STRIDE + d0] = q4;
    }
    __syncthreads();

    uint32_t qa[8][4];
    #pragma unroll
    for (int ks = 0; ks < 8; ks++) {
        qa[ks][0] = f2tf32(Qf[(wrow + g)     * KS_STRIDE + ks * 8 + t]);
        qa[ks][1] = f2tf32(Qf[(wrow + g + 8) * KS_STRIDE + ks * 8 + t]);
        qa[ks][2] = f2tf32(Qf[(wrow + g)     * KS_STRIDE + ks * 8 + t + 4]);
        qa[ks][3] = f2tf32(Qf[(wrow + g + 8) * KS_STRIDE + ks * 8 + t + 4]);
    }

    float oacc[8][4] = {};
    float m0 = -1e30f, m1 = -1e30f, l0 = 0.f, l1 = 0.f;

    const int NT = NS / 64;
    for (int kt = 0; kt < NT; kt++) {
        cp_wait<0>();
        __syncthreads();   // tile kt landed; all reads of stage buffer done

        // Issue tile kt+1 into the other stage (overlaps with compute below)
        if (kt + 1 < NT) {
            const uint32_t sb = ((kt + 1) & 1) * (ATT_STG * 4);
            #pragma unroll
            for (int it = 0; it < 4; it++) {
                const int key = akey + it * 16;
                const size_t src = ((size_t)((kt + 1) * 64 + key) << 6) + ad0;
                cp_async16(smb + sb + (uint32_t)(key * KS_STRIDE + ad0) * 4, &Kg[src]);
                cp_async16(smb + sb + (uint32_t)(64 * KS_STRIDE + key * VS_STRIDE + ad0) * 4, &Vg[src]);
            }
        }
        cp_commit();

        const uint32_t* Kb = sm + (kt & 1) * ATT_STG;
        const uint32_t* Vb = Kb + 64 * KS_STRIDE;

        // S = Q K^T (log2-scaled); K consumed as truncated tf32
        float sacc[8][4] = {};
        #pragma unroll
        for (int nt = 0; nt < 8; nt++) {
            const uint32_t* krow = &Kb[(nt * 8 + g) * KS_STRIDE + t];
            #pragma unroll
            for (int ks = 0; ks < 8; ks++) {
                uint32_t b[2];
                b[0] = krow[ks * 8];
                b[1] = krow[ks * 8 + 4];
                mma_tf32(sacc[nt], qa[ks], b);
            }
        }

        // Online softmax in log2 domain; build PV A-frags directly in regs
        float mx0 = -1e30f, mx1 = -1e30f;
        #pragma unroll
        for (int nt = 0; nt < 8; nt++) {
            mx0 = fmaxf(mx0, fmaxf(sacc[nt][0], sacc[nt][1]));
            mx1 = fmaxf(mx1, fmaxf(sacc[nt][2], sacc[nt][3]));
        }
        mx0 = fmaxf(mx0, __shfl_xor_sync(0xffffffffu, mx0, 1));
        mx0 = fmaxf(mx0, __shfl_xor_sync(0xffffffffu, mx0, 2));
        mx1 = fmaxf(mx1, __shfl_xor_sync(0xffffffffu, mx1, 1));
        mx1 = fmaxf(mx1, __shfl_xor_sync(0xffffffffu, mx1, 2));
        const float mn0 = fmaxf(m0, mx0), mn1 = fmaxf(m1, mx1);
        const float c0 = ex2(m0 - mn0), c1 = ex2(m1 - mn1);
        m0 = mn0; m1 = mn1;

        uint32_t pr[8][4];
        float s0 = 0.f, s1 = 0.f;
        #pragma unroll
        for (int nt = 0; nt < 8; nt++) {
            const float e0 = ex2(sacc[nt][0] - mn0);   // P[g][8nt+2t]
            const float e1 = ex2(sacc[nt][1] - mn0);   // P[g][8nt+2t+1]
            const float e2 = ex2(sacc[nt][2] - mn1);   // P[g+8][8nt+2t]
            const float e3 = ex2(sacc[nt][3] - mn1);   // P[g+8][8nt+2t+1]
            s0 += e0 + e1; s1 += e2 + e3;
            // A-frag (permuted keys): a0=row g pos t (key 2t)=e0,
            // a1=row g+8 pos t=e2, a2=row g pos t+4 (key 2t+1)=e1, a3=e3
            pr[nt][0] = f2tf32(e0); pr[nt][1] = f2tf32(e2);
            pr[nt][2] = f2tf32(e1); pr[nt][3] = f2tf32(e3);
            oacc[nt][0] *= c0; oacc[nt][1] *= c0;
            oacc[nt][2] *= c1; oacc[nt][3] *= c1;
        }
        s0 += __shfl_xor_sync(0xffffffffu, s0, 1);
        s0 += __shfl_xor_sync(0xffffffffu, s0, 2);
        s1 += __shfl_xor_sync(0xffffffffu, s1, 1);
        s1 += __shfl_xor_sync(0xffffffffu, s1, 2);
        l0 = l0 * c0 + s0;
        l1 = l1 * c1 + s1;

        // O += P V with permuted key order: B reads V rows 8ks+2t, 8ks+2t+1
        #pragma unroll
        for (int ks = 0; ks < 8; ks++) {
            const uint32_t* vr0 = &Vb[(ks * 8 + 2 * t)     * VS_STRIDE + g];
            const uint32_t* vr1 = &Vb[(ks * 8 + 2 * t + 1) * VS_STRIDE + g];
            #pragma unroll
            for (int nt = 0; nt < 8; nt++) {
                uint32_t b[2];
                b[0] = vr0[nt * 8];
                b[1] = vr1[nt * 8];
                mma_tf32(oacc[nt], pr[ks], b);
            }
        }
    }

    // Epilogue: O /= l -> ctx[s*NB+b][h*64+dk]
    const float inv0 = 1.f / l0, inv1 = 1.f / l1;
    const int h = hb >> 1, b = hb & 1;
    const int s_0 = qt * TQ + wrow + g;
    const int s_1 = s_0 + 8;
    #pragma unroll
    for (int nt = 0; nt < 8; nt++) {
        const int col = (h << 6) + nt * 8 + 2 * t;
        float2 o;
        o.x = oacc[nt][0] * inv0; o.y = oacc[nt][1] * inv0;
        *(float2*)&ctx[(size_t)(s_0 * NB + b) * DM + col] = o;
        o.x = oacc[nt][2] * inv1; o.y = oacc[nt][3] * inv1;
        *(float2*)&ctx[(size_t)(s_1 * NB + b) * DM + col] = o;
    }
}

// ---------------------------------------------------------------------------
extern "C" void kernel_launch(void* const* d_in, const int* in_sizes, int n_in,
                              void* d_out, int out_size)
{
    const float* query = (const float*)d_in[0];
    const float* key_  = (const float*)d_in[1];
    const float* value = (const float*)d_in[2];
    const float* Wq = (const float*)d_in[3];
    const float* bq = (const float*)d_in[4];
    const float* Wk = (const float*)d_in[5];
    const float* bk = (const float*)d_in[6];
    const float* Wv = (const float*)d_in[7];
    const float* bv = (const float*)d_in[8];
    const float* Wo = (const float*)d_in[9];
    const float* bo = (const float*)d_in[10];
    float* out = (float*)d_out;

    float *pQ, *pK, *pV, *pC;
    cudaGetSymbolAddress((void**)&pQ, g_Q);
    cudaGetSymbolAddress((void**)&pK, g_K);
    cudaGetSymbolAddress((void**)&pV, g_V);
    cudaGetSymbolAddress((void**)&pC, g_ctx);

    cudaFuncSetAttribute(attn_mma_kernel,
                         cudaFuncAttributeMaxDynamicSharedMemorySize, ATT_SMEM_BYTES);

    dim3 gq(DM / BN, NROWS / BM, 3);   // 8 x 32 x 3 = 768 CTAs
    qkv_gemm_kernel<<<gq, 256>>>(query, key_, value, Wq, Wk, Wv,
                                 bq, bk, bv, pQ, pK, pV);

    attn_mma_kernel<<<dim3(NS / TQ, NH * NB), 256, ATT_SMEM_BYTES>>>(pQ, pK, pV, pC);

    dim3 gg(DM / BN, NROWS / BM);      // 8 x 32 = 256 CTAs
    out_gemm_kernel<<<gg, 256>>>(pC, Wo, bo, out);
}